// round 1
// baseline (speedup 1.0000x reference)
#include <cuda_runtime.h>

// Problem constants
namespace {
constexpr int B_ = 128, U_ = 64, A_ = 64, C_ = 64;
constexpr int UA = U_ * A_;                 // 4096
constexpr float INV63 = 1.0f / 63.0f;
constexpr float INV3969 = (1.0f / 63.0f) * (1.0f / 63.0f);
}

// Scratch (static device allocations — no cudaMalloc allowed)
__device__ float g_h[(size_t)B_ * C_ * UA];     // hidden (h / h2), 134 MB
__device__ float g_m[(size_t)B_ * C_ * UA];     // stored msgs conv output (pre-post_users)
__device__ float g_s[(size_t)B_ * C_ * UA];     // stored relu(gamma conv2) (pre-post_users)
__device__ float g_colU_h[B_ * C_ * A_];        // sum over u of g_h
__device__ float g_colU_m[B_ * C_ * A_];        // sum over u of g_m
__device__ float g_colU_s[B_ * C_ * A_];        // sum over u of g_s
__device__ float g_rowA_m[B_ * C_ * U_];        // sum over a of g_m
__device__ float g_T_m[B_ * C_];                // full-plane sum of g_m

enum Variant { V_PHI1, V_PHIK1, V_PHI2, V_GAMMA1, V_GAMMAK1, V_GAMMA2, V_OUT5 };

// One CTA = (b, a-tile of 8), covers all 64 u's -> column sums over u computable in-CTA.
// 256 threads; thread owns positions (u0, a) and (u0+32, a) so each smem weight load
// feeds two FFMAs (LDS bandwidth : FFMA rate balance).
template<int VAR, int C_IN, int C_OUT, bool RELU, bool COLU, bool ROWA>
__global__ __launch_bounds__(256, 1)
void conv_kernel(const float* __restrict__ cgp,
                 const float* __restrict__ Wg,
                 const float* __restrict__ bg,
                 float* __restrict__ out5)
{
    __shared__ float Ws[C_IN * C_OUT];
    __shared__ float bs[C_OUT];
    __shared__ float red[COLU ? C_OUT * 8 : 1];

    const int t     = threadIdx.x;
    const int b     = blockIdx.y;
    const int atile = blockIdx.x;          // 0..7
    const int a     = atile * 8 + (t & 7);
    const int u0    = t >> 3;              // 0..31
    const int u1    = u0 + 32;
    const int pos0  = u0 * A_ + a;
    const int pos1  = u1 * A_ + a;
    const size_t bidx = (size_t)b * C_ * UA;
    const int cba  = b * C_ * A_ + a;      // + c*A_  -> colU index
    const int rb   = b * C_ * U_;          // + c*U_ + u -> rowA index

    // Load weights transposed into smem: Ws[c*C_OUT + o] = Wg[o*C_IN + c]
    for (int i = t; i < C_IN * C_OUT; i += 256) {
        int o = i % C_OUT, c = i / C_OUT;
        Ws[i] = Wg[o * C_IN + c];
    }
    if (t < C_OUT) bs[t] = bg[t];
    if constexpr (COLU) {
        for (int i = t; i < C_OUT * 8; i += 256) red[i] = 0.f;
    }
    __syncthreads();

    float acc0[C_OUT], acc1[C_OUT];
    #pragma unroll
    for (int o = 0; o < C_OUT; o++) { acc0[o] = 0.f; acc1[o] = 0.f; }

    auto fma_step = [&](int c, float x0, float x1) {
        #pragma unroll
        for (int o = 0; o < C_OUT; o++) {
            float w = Ws[c * C_OUT + o];
            acc0[o] = fmaf(w, x0, acc0[o]);
            acc1[o] = fmaf(w, x1, acc1[o]);
        }
    };
    // raw channels 0..31 of a 64ch tensor
    auto seg_raw = [&](const float* __restrict__ src, int wc0) {
        #pragma unroll 2
        for (int i = 0; i < 32; i++) {
            float x0 = src[bidx + (size_t)i * UA + pos0];
            float x1 = src[bidx + (size_t)i * UA + pos1];
            fma_step(wc0 + i, x0, x1);
        }
    };
    // post_users-transformed channels 32..63: (colU - x)/63
    auto seg_trans = [&](const float* __restrict__ src, const float* __restrict__ colU, int wc0) {
        #pragma unroll 2
        for (int i = 0; i < 32; i++) {
            int cc = 32 + i;
            float cs = colU[cba + cc * A_];
            float x0 = src[bidx + (size_t)cc * UA + pos0];
            float x1 = src[bidx + (size_t)cc * UA + pos1];
            fma_step(wc0 + i, (cs - x0) * INV63, (cs - x1) * INV63);
        }
    };
    // node agg channels, algebraically folded:
    //  c<32 : agg = (rowA - m)/63
    //  c>=32: agg = (T - rowA - colU + m)/63^2
    auto seg_agg = [&](int wc0) {
        #pragma unroll 2
        for (int cc = 0; cc < 32; cc++) {
            float ra0 = g_rowA_m[rb + cc * U_ + u0];
            float ra1 = g_rowA_m[rb + cc * U_ + u1];
            float m0  = g_m[bidx + (size_t)cc * UA + pos0];
            float m1  = g_m[bidx + (size_t)cc * UA + pos1];
            fma_step(wc0 + cc, (ra0 - m0) * INV63, (ra1 - m1) * INV63);
        }
        #pragma unroll 2
        for (int cc = 32; cc < 64; cc++) {
            float base = g_T_m[b * C_ + cc] - g_colU_m[cba + cc * A_];
            float ra0 = g_rowA_m[rb + cc * U_ + u0];
            float ra1 = g_rowA_m[rb + cc * U_ + u1];
            float m0  = g_m[bidx + (size_t)cc * UA + pos0];
            float m1  = g_m[bidx + (size_t)cc * UA + pos1];
            fma_step(wc0 + cc, (base - ra0 + m0) * INV3969, (base - ra1 + m1) * INV3969);
        }
    };

    float cg0 = 0.f, cg1 = 0.f;
    if (VAR == V_PHI1 || VAR == V_PHIK1 || VAR == V_GAMMA1) {
        cg0 = cgp[b * UA + pos0];
        cg1 = cgp[b * UA + pos1];
    }

    if constexpr (VAR == V_PHI1) {          // input concat(cg, cg): 2 identical channels
        fma_step(0, cg0, cg1);
        fma_step(1, cg0, cg1);
    } else if constexpr (VAR == V_PHIK1) {  // concat(cg, post_users(s))
        fma_step(0, cg0, cg1);
        seg_raw(g_s, 1);
        seg_trans(g_s, g_colU_s, 33);
    } else if constexpr (VAR == V_PHI2 || VAR == V_GAMMA2 || VAR == V_OUT5) {
        seg_raw(g_h, 0);                    // post_users(h)
        seg_trans(g_h, g_colU_h, 32);
    } else if constexpr (VAR == V_GAMMA1) { // concat(cg, agg)
        fma_step(0, cg0, cg1);
        seg_agg(1);
    } else if constexpr (VAR == V_GAMMAK1) { // concat(post_users(s), agg)
        seg_raw(g_s, 0);
        seg_trans(g_s, g_colU_s, 32);
        seg_agg(64);
    }

    // Output target per variant
    float* outp;
    float* colUp = nullptr;
    if constexpr (VAR == V_PHI1 || VAR == V_PHIK1 || VAR == V_GAMMA1 || VAR == V_GAMMAK1) {
        outp = g_h;  colUp = g_colU_h;
    } else if constexpr (VAR == V_PHI2) {
        outp = g_m;  colUp = g_colU_m;
    } else if constexpr (VAR == V_GAMMA2) {
        outp = g_s;  colUp = g_colU_s;
    } else {
        outp = out5;
    }

    const size_t obidx = (size_t)b * C_OUT * UA;
    const int lane = t & 31;
    #pragma unroll 1
    for (int o = 0; o < C_OUT; o++) {
        float v0 = acc0[o] + bs[o];
        float v1 = acc1[o] + bs[o];
        if (RELU) { v0 = fmaxf(v0, 0.f); v1 = fmaxf(v1, 0.f); }
        outp[obidx + (size_t)o * UA + pos0] = v0;
        outp[obidx + (size_t)o * UA + pos1] = v1;
        if constexpr (COLU) {
            // sum over u for fixed (o, a): lanes with same (t&7) differ in u
            float v = v0 + v1;
            v += __shfl_xor_sync(0xffffffffu, v, 8);
            v += __shfl_xor_sync(0xffffffffu, v, 16);
            if (lane < 8) atomicAdd(&red[o * 8 + lane], v);
        }
        if constexpr (ROWA) {
            // sum over the 8 a's of this tile for fixed (o, u); atomic partial to global
            float r0 = v0, r1 = v1;
            r0 += __shfl_xor_sync(0xffffffffu, r0, 1);
            r0 += __shfl_xor_sync(0xffffffffu, r0, 2);
            r0 += __shfl_xor_sync(0xffffffffu, r0, 4);
            r1 += __shfl_xor_sync(0xffffffffu, r1, 1);
            r1 += __shfl_xor_sync(0xffffffffu, r1, 2);
            r1 += __shfl_xor_sync(0xffffffffu, r1, 4);
            if ((lane & 7) == 0) {
                atomicAdd(&g_rowA_m[rb + o * U_ + u0], r0);
                atomicAdd(&g_rowA_m[rb + o * U_ + u1], r1);
            }
        }
    }
    if constexpr (COLU) {
        __syncthreads();
        for (int i = t; i < C_OUT * 8; i += 256) {
            int o = i >> 3, aa = i & 7;
            colUp[b * C_ * A_ + o * A_ + atile * 8 + aa] = red[i];
        }
    }
}

__global__ void zero_rowA_kernel()
{
    int i = blockIdx.x * 256 + threadIdx.x;
    if (i < B_ * C_ * U_) g_rowA_m[i] = 0.f;
}

__global__ void tkernel()
{
    int i = blockIdx.x * blockDim.x + threadIdx.x;
    if (i < B_ * C_) {
        float s = 0.f;
        const float* p = &g_colU_m[i * A_];
        #pragma unroll
        for (int aa = 0; aa < A_; aa++) s += p[aa];
        g_T_m[i] = s;
    }
}

extern "C" void kernel_launch(void* const* d_in, const int* in_sizes, int n_in,
                              void* d_out, int out_size)
{
    const float* cg        = (const float*)d_in[0];
    const float* phi1_W1   = (const float*)d_in[1];
    const float* phi1_b1   = (const float*)d_in[2];
    const float* phi1_W2   = (const float*)d_in[3];
    const float* phi1_b2   = (const float*)d_in[4];
    const float* phiK_W1   = (const float*)d_in[5];
    const float* phiK_b1   = (const float*)d_in[6];
    const float* phiK_W2   = (const float*)d_in[7];
    const float* phiK_b2   = (const float*)d_in[8];
    const float* gamma1_W1 = (const float*)d_in[9];
    const float* gamma1_b1 = (const float*)d_in[10];
    const float* gamma1_W2 = (const float*)d_in[11];
    const float* gamma1_b2 = (const float*)d_in[12];
    const float* gammaK_W1 = (const float*)d_in[13];
    const float* gammaK_b1 = (const float*)d_in[14];
    const float* gammaK_W2 = (const float*)d_in[15];
    const float* gammaK_b2 = (const float*)d_in[16];
    const float* gamma5_W1 = (const float*)d_in[17];
    const float* gamma5_b1 = (const float*)d_in[18];
    const float* gamma5_W2 = (const float*)d_in[19];
    const float* gamma5_b2 = (const float*)d_in[20];
    float* out = (float*)d_out;

    dim3 grid(A_ / 8, B_);   // (8, 128): a-tile x batch
    dim3 blk(256);

    auto phi2 = [&](const float* W, const float* b) {
        zero_rowA_kernel<<<(B_ * C_ * U_ + 255) / 256, 256>>>();
        conv_kernel<V_PHI2, 64, 64, false, true, true><<<grid, blk>>>(cg, W, b, nullptr);
        tkernel<<<(B_ * C_ + 127) / 128, 128>>>();
    };

    // iteration 0: phi1 + gamma1
    conv_kernel<V_PHI1, 2, 64, true, true, false><<<grid, blk>>>(cg, phi1_W1, phi1_b1, nullptr);
    phi2(phi1_W2, phi1_b2);
    conv_kernel<V_GAMMA1, 65, 64, true, true, false><<<grid, blk>>>(cg, gamma1_W1, gamma1_b1, nullptr);
    conv_kernel<V_GAMMA2, 64, 64, true, true, false><<<grid, blk>>>(cg, gamma1_W2, gamma1_b2, nullptr);

    // iterations 1..4: phiK[i] + (gammaK[i] | gamma5)
    for (int i = 0; i < 4; i++) {
        conv_kernel<V_PHIK1, 65, 64, true, true, false><<<grid, blk>>>(
            cg, phiK_W1 + (size_t)i * 64 * 65, phiK_b1 + i * 64, nullptr);
        phi2(phiK_W2 + (size_t)i * 64 * 64, phiK_b2 + i * 64);
        if (i < 3) {
            conv_kernel<V_GAMMAK1, 128, 64, true, true, false><<<grid, blk>>>(
                cg, gammaK_W1 + (size_t)i * 64 * 128, gammaK_b1 + i * 64, nullptr);
            conv_kernel<V_GAMMA2, 64, 64, true, true, false><<<grid, blk>>>(
                cg, gammaK_W2 + (size_t)i * 64 * 64, gammaK_b2 + i * 64, nullptr);
        } else {
            conv_kernel<V_GAMMAK1, 128, 64, true, true, false><<<grid, blk>>>(
                cg, gamma5_W1, gamma5_b1, nullptr);
            conv_kernel<V_OUT5, 64, 1, false, false, false><<<grid, blk>>>(
                cg, gamma5_W2, gamma5_b2, out);
        }
    }
}

// round 2
// speedup vs baseline: 4.9142x; 4.9142x over previous
#include <cuda_runtime.h>

namespace {
constexpr int B_ = 128, U_ = 64, A_ = 64, C_ = 64;
constexpr int UA = U_ * A_;
constexpr float INV63 = 1.0f / 63.0f;
constexpr float INV3969 = (1.0f / 63.0f) * (1.0f / 63.0f);
}

// Scratch (static device allocations — no cudaMalloc allowed)
__device__ float g_h[(size_t)B_ * C_ * UA];
__device__ float g_m[(size_t)B_ * C_ * UA];
__device__ float g_s[(size_t)B_ * C_ * UA];
__device__ float g_colU_h[B_ * C_ * A_];
__device__ float g_colU_m[B_ * C_ * A_];
__device__ float g_colU_s[B_ * C_ * A_];
__device__ float g_rowA_m[B_ * C_ * U_];
__device__ float g_T_m[B_ * C_];

enum Variant { V_PHI1, V_PHIK1, V_PHI2, V_GAMMA1, V_GAMMAK1, V_GAMMA2, V_OUT5 };

// ---- packed f32x2 helpers (sm_103a; ptxas never auto-fuses FFMA2) ----
__device__ __forceinline__ unsigned long long pk2(float lo, float hi) {
    unsigned long long r;
    asm("mov.b64 %0, {%1, %2};" : "=l"(r) : "f"(lo), "f"(hi));
    return r;
}
__device__ __forceinline__ void upk2(unsigned long long v, float& lo, float& hi) {
    asm("mov.b64 {%0, %1}, %2;" : "=f"(lo), "=f"(hi) : "l"(v));
}
__device__ __forceinline__ void ffma2(unsigned long long& acc,
                                      unsigned long long a, unsigned long long b) {
    asm("fma.rn.f32x2 %0, %1, %2, %0;" : "+l"(acc) : "l"(a), "l"(b));
}

// One CTA = (b, a-tile of 8), all 64 u's. 256 threads; thread owns (u0, u0+32).
// Accumulators: 32 packed f32x2 pairs (over output-channel pairs) per position.
template<int VAR, int C_IN, int C_OUT, bool RELU, bool COLU, bool ROWA>
__global__ __launch_bounds__(256, 1)
void conv_kernel(const float* __restrict__ cgp,
                 const float* __restrict__ Wg,
                 const float* __restrict__ bg,
                 float* __restrict__ out5)
{
    constexpr int NP = C_OUT / 2;                    // f32x2 pairs (C_OUT=64 path)
    constexpr int RED_SZ = COLU ? C_OUT * 64 : 1;    // [o][warp][a] = 64*8*8
    constexpr int SBUF_SZ = (C_IN * C_OUT > RED_SZ) ? C_IN * C_OUT : RED_SZ;
    __shared__ __align__(16) float sbuf[SBUF_SZ];    // weights, then reused as red
    __shared__ float bs[C_OUT];

    float* Ws = sbuf;

    const int t     = threadIdx.x;
    const int b     = blockIdx.y;
    const int atile = blockIdx.x;
    const int a     = atile * 8 + (t & 7);
    const int u0    = t >> 3;              // 0..31
    const int pos0  = u0 * A_ + a;
    const int pos1  = pos0 + 32 * A_;      // u0+32
    const size_t bidx = (size_t)b * C_ * UA;
    const int cba  = b * C_ * A_ + a;
    const int rb   = b * C_ * U_;

    // Weights transposed into smem: Ws[c*C_OUT + o] = Wg[o*C_IN + c]
    for (int i = t; i < C_IN * C_OUT; i += 256) {
        int o = i % C_OUT, c = i / C_OUT;
        Ws[i] = Wg[o * C_IN + c];
    }
    if (t < C_OUT) bs[t] = bg[t];
    __syncthreads();

    const unsigned long long* Ws64 = reinterpret_cast<const unsigned long long*>(Ws);

    // ---------------- main accumulation ----------------
    if constexpr (C_OUT >= 2) {
        unsigned long long accA[NP], accB[NP];
        #pragma unroll
        for (int j = 0; j < NP; j++) { accA[j] = 0ull; accB[j] = 0ull; }

        auto fma_step = [&](int c, float x0, float x1) {
            unsigned long long xx0 = pk2(x0, x0);
            unsigned long long xx1 = pk2(x1, x1);
            const unsigned long long* wrow = Ws64 + c * NP;
            #pragma unroll
            for (int j = 0; j < NP; j++) {
                unsigned long long w2 = wrow[j];       // LDS.64 broadcast
                ffma2(accA[j], w2, xx0);
                ffma2(accB[j], w2, xx1);
            }
        };
        auto seg_raw = [&](const float* __restrict__ src, int wc0) {
            #pragma unroll 2
            for (int i = 0; i < 32; i++) {
                float x0 = src[bidx + (size_t)i * UA + pos0];
                float x1 = src[bidx + (size_t)i * UA + pos1];
                fma_step(wc0 + i, x0, x1);
            }
        };
        auto seg_trans = [&](const float* __restrict__ src, const float* __restrict__ colU, int wc0) {
            #pragma unroll 2
            for (int i = 0; i < 32; i++) {
                int cc = 32 + i;
                float cs = colU[cba + cc * A_];
                float x0 = src[bidx + (size_t)cc * UA + pos0];
                float x1 = src[bidx + (size_t)cc * UA + pos1];
                fma_step(wc0 + i, (cs - x0) * INV63, (cs - x1) * INV63);
            }
        };
        auto seg_agg = [&](int wc0) {
            #pragma unroll 2
            for (int cc = 0; cc < 32; cc++) {
                float ra0 = g_rowA_m[rb + cc * U_ + u0];
                float ra1 = g_rowA_m[rb + cc * U_ + u0 + 32];
                float m0  = g_m[bidx + (size_t)cc * UA + pos0];
                float m1  = g_m[bidx + (size_t)cc * UA + pos1];
                fma_step(wc0 + cc, (ra0 - m0) * INV63, (ra1 - m1) * INV63);
            }
            #pragma unroll 2
            for (int cc = 32; cc < 64; cc++) {
                float base = g_T_m[b * C_ + cc] - g_colU_m[cba + cc * A_];
                float ra0 = g_rowA_m[rb + cc * U_ + u0];
                float ra1 = g_rowA_m[rb + cc * U_ + u0 + 32];
                float m0  = g_m[bidx + (size_t)cc * UA + pos0];
                float m1  = g_m[bidx + (size_t)cc * UA + pos1];
                fma_step(wc0 + cc, (base - ra0 + m0) * INV3969, (base - ra1 + m1) * INV3969);
            }
        };

        float cg0 = 0.f, cg1 = 0.f;
        if (VAR == V_PHI1 || VAR == V_PHIK1 || VAR == V_GAMMA1) {
            cg0 = cgp[b * UA + pos0];
            cg1 = cgp[b * UA + pos1];
        }

        if constexpr (VAR == V_PHI1) {
            fma_step(0, cg0, cg1);
            fma_step(1, cg0, cg1);
        } else if constexpr (VAR == V_PHIK1) {
            fma_step(0, cg0, cg1);
            seg_raw(g_s, 1);
            seg_trans(g_s, g_colU_s, 33);
        } else if constexpr (VAR == V_PHI2 || VAR == V_GAMMA2) {
            seg_raw(g_h, 0);
            seg_trans(g_h, g_colU_h, 32);
        } else if constexpr (VAR == V_GAMMA1) {
            fma_step(0, cg0, cg1);
            seg_agg(1);
        } else if constexpr (VAR == V_GAMMAK1) {
            seg_raw(g_s, 0);
            seg_trans(g_s, g_colU_s, 32);
            seg_agg(64);
        }

        // Output target
        float* outp; float* colUp = nullptr;
        if constexpr (VAR == V_PHI1 || VAR == V_PHIK1 || VAR == V_GAMMA1 || VAR == V_GAMMAK1) {
            outp = g_h;  colUp = g_colU_h;
        } else if constexpr (VAR == V_PHI2) {
            outp = g_m;  colUp = g_colU_m;
        } else {
            outp = g_s;  colUp = g_colU_s;
        }

        const size_t obidx = (size_t)b * C_OUT * UA;
        const int lane = t & 31;
        const int wid  = t >> 5;
        float* red = sbuf;               // reuse weight smem for cross-warp reduce

        if constexpr (COLU) __syncthreads();   // all warps done reading Ws

        #pragma unroll
        for (int j = 0; j < NP; j++) {
            float v0a, v0b, v1a, v1b;
            upk2(accA[j], v0a, v0b);     // pos0: o=2j, 2j+1
            upk2(accB[j], v1a, v1b);     // pos1
            v0a += bs[2*j];   v0b += bs[2*j+1];
            v1a += bs[2*j];   v1b += bs[2*j+1];
            if (RELU) {
                v0a = fmaxf(v0a, 0.f); v0b = fmaxf(v0b, 0.f);
                v1a = fmaxf(v1a, 0.f); v1b = fmaxf(v1b, 0.f);
            }
            outp[obidx + (size_t)(2*j)   * UA + pos0] = v0a;
            outp[obidx + (size_t)(2*j+1) * UA + pos0] = v0b;
            outp[obidx + (size_t)(2*j)   * UA + pos1] = v1a;
            outp[obidx + (size_t)(2*j+1) * UA + pos1] = v1b;
            if constexpr (COLU) {
                float va = v0a + v1a;
                float vb = v0b + v1b;
                va += __shfl_xor_sync(0xffffffffu, va, 8);
                va += __shfl_xor_sync(0xffffffffu, va, 16);
                vb += __shfl_xor_sync(0xffffffffu, vb, 8);
                vb += __shfl_xor_sync(0xffffffffu, vb, 16);
                if (lane < 8) {
                    red[(2*j)   * 64 + wid * 8 + lane] = va;   // private per-warp slice
                    red[(2*j+1) * 64 + wid * 8 + lane] = vb;
                }
            }
            if constexpr (ROWA) {
                float r0a = v0a, r1a = v1a, r0b = v0b, r1b = v1b;
                #pragma unroll
                for (int m = 1; m <= 4; m <<= 1) {
                    r0a += __shfl_xor_sync(0xffffffffu, r0a, m);
                    r1a += __shfl_xor_sync(0xffffffffu, r1a, m);
                    r0b += __shfl_xor_sync(0xffffffffu, r0b, m);
                    r1b += __shfl_xor_sync(0xffffffffu, r1b, m);
                }
                if ((lane & 7) == 0) {
                    atomicAdd(&g_rowA_m[rb + (2*j)   * U_ + u0],      r0a);
                    atomicAdd(&g_rowA_m[rb + (2*j)   * U_ + u0 + 32], r1a);
                    atomicAdd(&g_rowA_m[rb + (2*j+1) * U_ + u0],      r0b);
                    atomicAdd(&g_rowA_m[rb + (2*j+1) * U_ + u0 + 32], r1b);
                }
            }
        }
        if constexpr (COLU) {
            __syncthreads();
            for (int i = t; i < C_OUT * 8; i += 256) {
                int o = i >> 3, aa = i & 7;
                float s = 0.f;
                #pragma unroll
                for (int w = 0; w < 8; w++) s += red[o * 64 + w * 8 + aa];
                colUp[b * C_ * A_ + o * A_ + atile * 8 + aa] = s;
            }
        }
    } else {
        // -------- C_OUT == 1 (final output layer): scalar path --------
        float a0 = 0.f, a1 = 0.f;
        #pragma unroll 2
        for (int i = 0; i < 32; i++) {
            float w = Ws[i];                       // Ws[c*1 + 0]
            a0 = fmaf(w, g_h[bidx + (size_t)i * UA + pos0], a0);
            a1 = fmaf(w, g_h[bidx + (size_t)i * UA + pos1], a1);
        }
        #pragma unroll 2
        for (int i = 0; i < 32; i++) {
            int cc = 32 + i;
            float w = Ws[cc];
            float cs = g_colU_h[cba + cc * A_];
            float x0 = g_h[bidx + (size_t)cc * UA + pos0];
            float x1 = g_h[bidx + (size_t)cc * UA + pos1];
            a0 = fmaf(w, (cs - x0) * INV63, a0);
            a1 = fmaf(w, (cs - x1) * INV63, a1);
        }
        out5[(size_t)b * UA + pos0] = a0 + bs[0];
        out5[(size_t)b * UA + pos1] = a1 + bs[0];
    }
}

__global__ void zero_rowA_kernel()
{
    int i = blockIdx.x * 256 + threadIdx.x;
    if (i < B_ * C_ * U_) g_rowA_m[i] = 0.f;
}

__global__ void tkernel()
{
    int i = blockIdx.x * blockDim.x + threadIdx.x;
    if (i < B_ * C_) {
        float s = 0.f;
        const float* p = &g_colU_m[i * A_];
        #pragma unroll
        for (int aa = 0; aa < A_; aa++) s += p[aa];
        g_T_m[i] = s;
    }
}

extern "C" void kernel_launch(void* const* d_in, const int* in_sizes, int n_in,
                              void* d_out, int out_size)
{
    const float* cg        = (const float*)d_in[0];
    const float* phi1_W1   = (const float*)d_in[1];
    const float* phi1_b1   = (const float*)d_in[2];
    const float* phi1_W2   = (const float*)d_in[3];
    const float* phi1_b2   = (const float*)d_in[4];
    const float* phiK_W1   = (const float*)d_in[5];
    const float* phiK_b1   = (const float*)d_in[6];
    const float* phiK_W2   = (const float*)d_in[7];
    const float* phiK_b2   = (const float*)d_in[8];
    const float* gamma1_W1 = (const float*)d_in[9];
    const float* gamma1_b1 = (const float*)d_in[10];
    const float* gamma1_W2 = (const float*)d_in[11];
    const float* gamma1_b2 = (const float*)d_in[12];
    const float* gammaK_W1 = (const float*)d_in[13];
    const float* gammaK_b1 = (const float*)d_in[14];
    const float* gammaK_W2 = (const float*)d_in[15];
    const float* gammaK_b2 = (const float*)d_in[16];
    const float* gamma5_W1 = (const float*)d_in[17];
    const float* gamma5_b1 = (const float*)d_in[18];
    const float* gamma5_W2 = (const float*)d_in[19];
    const float* gamma5_b2 = (const float*)d_in[20];
    float* out = (float*)d_out;

    dim3 grid(A_ / 8, B_);
    dim3 blk(256);

    auto phi2 = [&](const float* W, const float* b) {
        zero_rowA_kernel<<<(B_ * C_ * U_ + 255) / 256, 256>>>();
        conv_kernel<V_PHI2, 64, 64, false, true, true><<<grid, blk>>>(cg, W, b, nullptr);
        tkernel<<<(B_ * C_ + 127) / 128, 128>>>();
    };

    conv_kernel<V_PHI1, 2, 64, true, true, false><<<grid, blk>>>(cg, phi1_W1, phi1_b1, nullptr);
    phi2(phi1_W2, phi1_b2);
    conv_kernel<V_GAMMA1, 65, 64, true, true, false><<<grid, blk>>>(cg, gamma1_W1, gamma1_b1, nullptr);
    conv_kernel<V_GAMMA2, 64, 64, true, true, false><<<grid, blk>>>(cg, gamma1_W2, gamma1_b2, nullptr);

    for (int i = 0; i < 4; i++) {
        conv_kernel<V_PHIK1, 65, 64, true, true, false><<<grid, blk>>>(
            cg, phiK_W1 + (size_t)i * 64 * 65, phiK_b1 + i * 64, nullptr);
        phi2(phiK_W2 + (size_t)i * 64 * 64, phiK_b2 + i * 64);
        if (i < 3) {
            conv_kernel<V_GAMMAK1, 128, 64, true, true, false><<<grid, blk>>>(
                cg, gammaK_W1 + (size_t)i * 64 * 128, gammaK_b1 + i * 64, nullptr);
            conv_kernel<V_GAMMA2, 64, 64, true, true, false><<<grid, blk>>>(
                cg, gammaK_W2 + (size_t)i * 64 * 64, gammaK_b2 + i * 64, nullptr);
        } else {
            conv_kernel<V_GAMMAK1, 128, 64, true, true, false><<<grid, blk>>>(
                cg, gamma5_W1, gamma5_b1, nullptr);
            conv_kernel<V_OUT5, 64, 1, false, false, false><<<grid, blk>>>(
                cg, gamma5_W2, gamma5_b2, out);
        }
    }
}